// round 5
// baseline (speedup 1.0000x reference)
#include <cuda_runtime.h>

#define FULLMASK 0xffffffffu
typedef unsigned long long u64;

constexpr int NPB  = 4;          // warps (nodes) per block
constexpr int MAXN = 50001;

__device__ int g_starts[MAXN];   // CSR row starts

// ---------- packed f32x2 helpers ----------
__device__ __forceinline__ u64 pack2(float lo, float hi) {
    u64 r; asm("mov.b64 %0,{%1,%2};" : "=l"(r) : "f"(lo), "f"(hi)); return r;
}
__device__ __forceinline__ u64 splat2(float v) {
    u64 r; asm("mov.b64 %0,{%1,%1};" : "=l"(r) : "f"(v)); return r;
}
__device__ __forceinline__ void unpack2(u64 v, float& lo, float& hi) {
    asm("mov.b64 {%0,%1},%2;" : "=f"(lo), "=f"(hi) : "l"(v));
}
__device__ __forceinline__ u64 fma2(u64 a, u64 b, u64 c) {
    u64 d; asm("fma.rn.f32x2 %0,%1,%2,%3;" : "=l"(d) : "l"(a), "l"(b), "l"(c)); return d;
}

// ---------- kernel 0: build row starts from sorted seg ----------
__global__ void build_starts_kernel(const int* __restrict__ seg, int N, int E) {
    int e = blockIdx.x * blockDim.x + threadIdx.x;
    if (e >= E) return;
    int s = seg[e];
    int p = (e == 0) ? -1 : seg[e - 1];
    for (int n = p + 1; n <= s; ++n) g_starts[n] = e;
    if (e == E - 1)
        for (int n = s + 1; n <= N; ++n) g_starts[n] = E;
}

// 32-lane reduce of 8 partials with head splitting; lane ends with head lane>>2
__device__ __forceinline__ float reduce8_32(const float p[8], int lane) {
    bool b4 = (lane & 16) != 0;
    float q[4];
#pragma unroll
    for (int j = 0; j < 4; ++j) {
        float send = b4 ? p[j] : p[j + 4];
        float recv = __shfl_xor_sync(FULLMASK, send, 16);
        q[j] = (b4 ? p[j + 4] : p[j]) + recv;
    }
    bool b3 = (lane & 8) != 0;
    float r[2];
#pragma unroll
    for (int j = 0; j < 2; ++j) {
        float send = b3 ? q[j] : q[j + 2];
        float recv = __shfl_xor_sync(FULLMASK, send, 8);
        r[j] = (b3 ? q[j + 2] : q[j]) + recv;
    }
    bool b2 = (lane & 4) != 0;
    float send = b2 ? r[0] : r[1];
    float recv = __shfl_xor_sync(FULLMASK, send, 4);
    float s = (b2 ? r[1] : r[0]) + recv;
    s += __shfl_xor_sync(FULLMASK, s, 2);
    s += __shfl_xor_sync(FULLMASK, s, 1);
    return s;
}

__device__ __forceinline__ float elu1(float x) {
    return x > 0.0f ? x : (__expf(x) - 1.0f);
}

// ---------- main fused kernel: warp/node, 2 edges per iter, 16 lanes per edge ----------
__global__ __launch_bounds__(128, 6)
void gat_agg_kernel(const float* __restrict__ features,
                    const float* __restrict__ emb,
                    const float* __restrict__ attn1,
                    const float* __restrict__ attn2,
                    float*       __restrict__ out,
                    int N)
{
    const int lane = threadIdx.x & 31;
    const int wid  = threadIdx.x >> 5;
    const int n    = blockIdx.x * NPB + wid;
    if (n >= N) return;

    const int g    = lane >> 4;        // edge slot within pair (0/1)
    const int i    = lane & 15;        // dim-quad index: dims [4i, 4i+4)
    const int head = i >> 1;           // score head this lane ends with (dup over i&1)

    const int s0 = g_starts[n];
    const int e0 = g_starts[n + 1];

    // ---- attn2 resident in registers: 8 heads x this lane's dim quad ----
    u64 w2r[8][2];
    const float4* __restrict__ a2f4 = (const float4*)attn2;
#pragma unroll
    for (int h = 0; h < 8; ++h) {
        float4 t = a2f4[h * 16 + i];
        w2r[h][0] = pack2(t.x, t.y);
        w2r[h][1] = pack2(t.z, t.w);
    }

    // ---- a1 for this lane's score head (once per node) ----
    float a1_i;
    {
        float2 f = *(const float2*)(features + (size_t)n * 64 + 2 * lane);
        float p1[8];
#pragma unroll
        for (int h = 0; h < 8; ++h) {
            float2 a = *(const float2*)(attn1 + h * 64 + 2 * lane);
            p1[h] = f.x * a.x + f.y * a.y;
        }
        float a1h = reduce8_32(p1, lane);             // lane -> head lane>>2
        a1_i = __shfl_sync(FULLMASK, a1h, 4 * head);
    }

    const float4* __restrict__ ef4 = (const float4*)emb;
    const u64 Z = 0ull;

    u64 acc[4][2];                                    // heads [4g,4g+4) x dim pairs
#pragma unroll
    for (int hp = 0; hp < 4; ++hp) { acc[hp][0] = Z; acc[hp][1] = Z; }
    float dn = 0.0f;

    const int nIter = (e0 - s0 + 1) >> 1;

    float4 F;                                         // prefetched emb quad
    if (nIter > 0) {
        int ec = min(s0 + g, e0 - 1);
        F = ef4[(size_t)ec * 16 + i];
    }

    for (int t = 0; t < nIter; ++t) {
        const int e = s0 + 2 * t + g;
        const bool valid = e < e0;
        float4 Fc = F;
        if (t + 1 < nIter) {                          // prefetch next pair (MLP=2)
            int en = min(e + 2, e0 - 1);
            F = ef4[(size_t)en * 16 + i];
        }

        u64 ep0 = pack2(Fc.x, Fc.y);
        u64 ep1 = pack2(Fc.z, Fc.w);

        // ---- phase A: 8 head-partials over this lane's 4 dims ----
        float p[8];
#pragma unroll
        for (int h = 0; h < 8; ++h) {
            u64 tt = fma2(ep0, w2r[h][0], Z);
            tt = fma2(ep1, w2r[h][1], tt);
            float lo, hi; unpack2(tt, lo, hi);
            p[h] = lo + hi;
        }

        // 16-lane head-splitting tree reduce (head bits from i bits 3,2,1)
        bool b3 = (i & 8) != 0;
        float q[4];
#pragma unroll
        for (int j = 0; j < 4; ++j) {
            float send = b3 ? p[j] : p[j + 4];
            float recv = __shfl_xor_sync(FULLMASK, send, 8);
            q[j] = (b3 ? p[j + 4] : p[j]) + recv;
        }
        bool b2 = (i & 4) != 0;
        float r[2];
#pragma unroll
        for (int j = 0; j < 2; ++j) {
            float send = b2 ? q[j] : q[j + 2];
            float recv = __shfl_xor_sync(FULLMASK, send, 4);
            r[j] = (b2 ? q[j + 2] : q[j]) + recv;
        }
        bool b1 = (i & 2) != 0;
        float send = b1 ? r[0] : r[1];
        float recv = __shfl_xor_sync(FULLMASK, send, 2);
        float s = (b1 ? r[1] : r[0]) + recv;
        s += __shfl_xor_sync(FULLMASK, s, 1);         // exact dup over i&1

        float sc = s + a1_i;
        sc = fmaxf(sc, 0.2f * sc);                    // leaky relu
        float w = valid ? __expf(sc) : 0.0f;          // no-max softmax (bounded scores)
        dn += w;

        // ---- phase B: rank-2 update from registers (no memory) ----
        float ox = __shfl_xor_sync(FULLMASK, Fc.x, 16);
        float oy = __shfl_xor_sync(FULLMASK, Fc.y, 16);
        float oz = __shfl_xor_sync(FULLMASK, Fc.z, 16);
        float ow = __shfl_xor_sync(FULLMASK, Fc.w, 16);
        u64 oq0 = pack2(ox, oy);
        u64 oq1 = pack2(oz, ow);

#pragma unroll
        for (int hp = 0; hp < 4; ++hp) {
            // weight of own edge (slot g) for head 4g+hp lives at lane 24g+2hp;
            // weight of other edge (slot 1-g) at lane 16-8g+2hp
            float wOwn = __shfl_sync(FULLMASK, w, 24 * g + 2 * hp);
            float wOth = __shfl_sync(FULLMASK, w, 16 - 8 * g + 2 * hp);
            u64 wOs = splat2(wOwn);
            u64 wTs = splat2(wOth);
            acc[hp][0] = fma2(ep0, wOs, acc[hp][0]);
            acc[hp][1] = fma2(ep1, wOs, acc[hp][1]);
            acc[hp][0] = fma2(oq0, wTs, acc[hp][0]);
            acc[hp][1] = fma2(oq1, wTs, acc[hp][1]);
        }
    }

    // ---- denominator: dup lanes are bit-identical -> sum is exactly 2x denom ----
    dn += __shfl_xor_sync(FULLMASK, dn, 1);
    dn += __shfl_xor_sync(FULLMASK, dn, 16);
    float inv = dn > 0.0f ? 2.0f * __frcp_rn(dn) : 1.0f;   // x2 compensates dup

    // ---- finalize: normalize, ELU, store (lane: heads [4g,4g+4), dims [4i,4i+4)) ----
    float* op = out + (size_t)n * 512;
#pragma unroll
    for (int hp = 0; hp < 4; ++hp) {
        float ih = __shfl_sync(FULLMASK, inv, 8 * g + 2 * hp);
        float v0, v1, v2, v3;
        unpack2(acc[hp][0], v0, v1);
        unpack2(acc[hp][1], v2, v3);
        float4 o;
        o.x = elu1(v0 * ih);
        o.y = elu1(v1 * ih);
        o.z = elu1(v2 * ih);
        o.w = elu1(v3 * ih);
        *(float4*)(op + (4 * g + hp) * 64 + 4 * i) = o;
    }
}

extern "C" void kernel_launch(void* const* d_in, const int* in_sizes, int n_in,
                              void* d_out, int out_size) {
    const float* features = (const float*)d_in[0];
    const float* emb      = (const float*)d_in[1];
    const float* attn1    = (const float*)d_in[2];
    const float* attn2    = (const float*)d_in[3];
    const int*   seg      = (const int*)d_in[4];
    float* out = (float*)d_out;

    int N = in_sizes[0] / 64;    // 50000
    int E = in_sizes[4];         // 1250000

    build_starts_kernel<<<(E + 255) / 256, 256>>>(seg, N, E);

    int blocks = (N + NPB - 1) / NPB;
    gat_agg_kernel<<<blocks, NPB * 32>>>(features, emb, attn1, attn2, out, N);
}